// round 9
// baseline (speedup 1.0000x reference)
#include <cuda_runtime.h>

#define B_  4
#define H_  256
#define W_  256
#define CIN 256
#define CM  64
#define HW  (H_*W_)

// ---------------- scratch (static device memory — no allocations) ----------------
__device__ float g_y[(size_t)B_*CM*HW];       // 64 MB: conv_in output
__device__ float g_edge[(size_t)B_*CM*HW];    // 64 MB: edge_raw (pre-normalization)
__device__ float g_wr[CIN*CM];                // w_in tf32-rounded [c][o]
__device__ float g_or[B_*CM*CM];              // folded out weights tf32-rounded [b][c][o]
__device__ float g_scale[B_*CM];              // sigmoid(..)*inv_max per (b,c)
__device__ float g_sums[B_*CM];               // per-(b,c) edge sums
__device__ unsigned int g_maxbits;            // global max (float bits, edge>=0)

// Separable gaussian taps (sigma=2, size=5)
static constexpr double GE0 = 0.6065306597126334;
static constexpr double GE1 = 0.8824969025845955;
static constexpr double GSUM = 2.0*(GE0+GE1)+1.0;
static constexpr float G0 = (float)(GE0/GSUM);
static constexpr float G1 = (float)(GE1/GSUM);
static constexpr float G2 = (float)(1.0/GSUM);

// ---------------- tf32 / async helpers ----------------
__device__ __forceinline__ float tf32_big(float x) {
    unsigned r;
    asm("cvt.rna.tf32.f32 %0, %1;" : "=r"(r) : "f"(x));
    return __uint_as_float(r);
}
__device__ __forceinline__ unsigned tf32_bits(float x) {
    unsigned r;
    asm("cvt.rna.tf32.f32 %0, %1;" : "=r"(r) : "f"(x));
    return r;
}
__device__ __forceinline__ void mma8(float* c, const unsigned* a, unsigned b0, unsigned b1) {
    asm("mma.sync.aligned.m16n8k8.row.col.f32.tf32.tf32.f32 "
        "{%0,%1,%2,%3}, {%4,%5,%6,%7}, {%8,%9}, {%0,%1,%2,%3};"
        : "+f"(c[0]), "+f"(c[1]), "+f"(c[2]), "+f"(c[3])
        : "r"(a[0]), "r"(a[1]), "r"(a[2]), "r"(a[3]), "r"(b0), "r"(b1));
}
__device__ __forceinline__ void cp16(void* smem, const void* g) {
    unsigned s = (unsigned)__cvta_generic_to_shared(smem);
    asm volatile("cp.async.ca.shared.global [%0], [%1], 16;" :: "r"(s), "l"(g));
}
#define CP_COMMIT() asm volatile("cp.async.commit_group;" ::: "memory")
#define CP_WAIT0()  asm volatile("cp.async.wait_group 0;" ::: "memory")

// smem strides (floats); 136,72 == 8 mod 32 -> conflict-free frag LDS; 132 -> conflict-free STS
#define ASTR 136
#define BSTR 72
#define OSTR 132

struct alignas(16) GSmem {
    union {
        struct {
            float xr[2][16*ASTR];   // raw x chunk, double-buffered
            float wr[2][16*BSTR];   // tf32-rounded w chunk
        } s;
        float outs[64*OSTR];
    };
};

// ---------------- 1-term TF32 GEMM body: [KTOT ch] x [128 px] tile -> 64 outs ----------------
// CVT_A=false: feed raw fp32 bits as tf32 (HW truncation; 2x rounding RMS, no cvt latency).
template<int KTOT, bool CVT_A>
__device__ __forceinline__ void gemm_body(const float* __restrict__ xpx,
                                          const float* __restrict__ wrp,
                                          const float* __restrict__ bias,
                                          float* __restrict__ yout) {
    __shared__ GSmem sm;
    const int t = threadIdx.x;
    const int l = t & 31, wid = t >> 5;
    const int wm = wid & 3, wn = wid >> 2;      // 4 x 2 warp grid (px x out)
    const int lr = l >> 2, lc = l & 3;

    float acc[2][4][4];
#pragma unroll
    for (int mt = 0; mt < 2; ++mt)
#pragma unroll
        for (int nt = 0; nt < 4; ++nt)
#pragma unroll
            for (int q = 0; q < 4; ++q) acc[mt][nt][q] = 0.f;

    // per-thread load indices
    const int xk0 = t >> 5,       xc0 = (t & 31) * 4;   // 2 sub-chunks of 8 ch
    const int wk  = t >> 4,       wc  = (t & 15) * 4;

    // prologue: load chunk 0 into buf 0
    {
        cp16(&sm.s.xr[0][xk0*ASTR + xc0],      xpx + (size_t)xk0*HW + xc0);
        cp16(&sm.s.xr[0][(xk0+8)*ASTR + xc0],  xpx + (size_t)(xk0+8)*HW + xc0);
        cp16(&sm.s.wr[0][wk*BSTR + wc],        wrp + wk*CM + wc);
        CP_COMMIT();
    }

    int buf = 0;
    for (int kc = 0; kc < KTOT; kc += 16) {
        CP_WAIT0();
        __syncthreads();

        // issue next chunk into the other buffer (overlaps with MMA below)
        if (kc + 16 < KTOT) {
            int nb = buf ^ 1, kn = kc + 16;
            cp16(&sm.s.xr[nb][xk0*ASTR + xc0],     xpx + (size_t)(kn+xk0)*HW + xc0);
            cp16(&sm.s.xr[nb][(xk0+8)*ASTR + xc0], xpx + (size_t)(kn+xk0+8)*HW + xc0);
            cp16(&sm.s.wr[nb][wk*BSTR + wc],       wrp + (kn+wk)*CM + wc);
            CP_COMMIT();
        }

        const float* __restrict__ xb = sm.s.xr[buf];
        const float* __restrict__ wb = sm.s.wr[buf];

#pragma unroll
        for (int k8 = 0; k8 < 16; k8 += 8) {
            const int kk = k8 + lc;
            unsigned A[2][4];
#pragma unroll
            for (int mt = 0; mt < 2; ++mt) {
                const int px = wm*32 + mt*16 + lr;
                if (CVT_A) {
                    A[mt][0] = tf32_bits(xb[kk*ASTR + px]);
                    A[mt][1] = tf32_bits(xb[kk*ASTR + px + 8]);
                    A[mt][2] = tf32_bits(xb[(kk+4)*ASTR + px]);
                    A[mt][3] = tf32_bits(xb[(kk+4)*ASTR + px + 8]);
                } else {
                    A[mt][0] = __float_as_uint(xb[kk*ASTR + px]);
                    A[mt][1] = __float_as_uint(xb[kk*ASTR + px + 8]);
                    A[mt][2] = __float_as_uint(xb[(kk+4)*ASTR + px]);
                    A[mt][3] = __float_as_uint(xb[(kk+4)*ASTR + px + 8]);
                }
            }
#pragma unroll
            for (int nt = 0; nt < 4; ++nt) {
                const int n = wn*32 + nt*8 + lr;
                unsigned B0 = __float_as_uint(wb[kk*BSTR + n]);
                unsigned B1 = __float_as_uint(wb[(kk+4)*BSTR + n]);
#pragma unroll
                for (int mt = 0; mt < 2; ++mt)
                    mma8(acc[mt][nt], A[mt], B0, B1);
            }
        }
        __syncthreads();
        buf ^= 1;
    }

    // stage C frags to smem, then coalesced store + bias
#pragma unroll
    for (int mt = 0; mt < 2; ++mt) {
#pragma unroll
        for (int nt = 0; nt < 4; ++nt) {
            int px = wm*32 + mt*16 + lr;
            int o  = wn*32 + nt*8 + 2*lc;
            sm.outs[o*OSTR + px]           = acc[mt][nt][0];
            sm.outs[(o+1)*OSTR + px]       = acc[mt][nt][1];
            sm.outs[o*OSTR + px + 8]       = acc[mt][nt][2];
            sm.outs[(o+1)*OSTR + px + 8]   = acc[mt][nt][3];
        }
    }
    __syncthreads();
#pragma unroll
    for (int p = 0; p < 8; ++p) {
        int i = p*256 + t;
        int o = i >> 5, c4 = (i & 31) * 4;
        float4 v = *(const float4*)&sm.outs[o*OSTR + c4];
        float bv = bias[o];
        v.x += bv; v.y += bv; v.z += bv; v.w += bv;
        *(float4*)(yout + (size_t)o*HW + c4) = v;
    }
}

// ---------------- init: tf32-round w_in, zero reductions ----------------
__global__ void k_init(const float* __restrict__ w_in) {
    int i = blockIdx.x*256 + threadIdx.x;    // 16384 = CIN*CM
    int c = i >> 6, o = i & 63;
    g_wr[i] = tf32_big(w_in[o*CIN + c]);
    if (i < B_*CM) g_sums[i] = 0.f;
    if (i == 0) g_maxbits = 0u;
}

// ---------------- conv1x1 in: [B,256,HW] -> [B,64,HW] ----------------
__global__ __launch_bounds__(256, 2)
void k_conv_in(const float* __restrict__ x, const float* __restrict__ b_in) {
    int bx = blockIdx.x;
    int b = bx >> 9, tile = bx & 511;
    gemm_body<CIN, false>(x + (size_t)b*CIN*HW + tile*128, g_wr, b_in,
                          g_y + (size_t)b*CM*HW + tile*128);
}

// ---------------- fused gaussian(separable) + scharr/laplacian + reductions ----------------
#define TW 64
#define TH 32
__global__ __launch_bounds__(256)
void k_edge() {
    __shared__ float ysh[TH+6][TW+8];
    __shared__ float tsh[TH+6][TW+4];
    __shared__ float smsh[TH+2][TW+4];

    const int t  = threadIdx.x;
    const int x0 = blockIdx.x*TW, y0 = blockIdx.y*TH;
    const int bc = blockIdx.z;
    const float* __restrict__ yp = g_y    + (size_t)bc*HW;
    float* __restrict__       ep = g_edge + (size_t)bc*HW;

    for (int i = t; i < (TH+6)*(TW+6); i += 256) {
        int rr = i/(TW+6), cc = i - rr*(TW+6);
        int gr = y0 - 3 + rr, gc = x0 - 3 + cc;
        float v = 0.f;
        if ((unsigned)gr < H_ && (unsigned)gc < W_) v = yp[gr*W_ + gc];
        ysh[rr][cc] = v;
    }
    __syncthreads();

    for (int i = t; i < (TH+6)*(TW+2); i += 256) {
        int rr = i/(TW+2), jj = i - rr*(TW+2);
        tsh[rr][jj] = G0*(ysh[rr][jj] + ysh[rr][jj+4])
                    + G1*(ysh[rr][jj+1] + ysh[rr][jj+3])
                    + G2* ysh[rr][jj+2];
    }
    __syncthreads();

    for (int i = t; i < (TH+2)*(TW+2); i += 256) {
        int ii = i/(TW+2), jj = i - ii*(TW+2);
        int sr = y0 - 1 + ii, sc = x0 - 1 + jj;
        float v = 0.f;
        if ((unsigned)sr < H_ && (unsigned)sc < W_)
            v = G0*(tsh[ii][jj] + tsh[ii+4][jj])
              + G1*(tsh[ii+1][jj] + tsh[ii+3][jj])
              + G2* tsh[ii+2][jj];
        smsh[ii][jj] = v;
    }
    __syncthreads();

    float lsum = 0.f, lmax = 0.f;
    for (int i = t; i < TH*TW; i += 256) {
        int ty = i >> 6, tx = i & 63;
        float a  = smsh[ty  ][tx], bb = smsh[ty  ][tx+1], c2 = smsh[ty  ][tx+2];
        float d  = smsh[ty+1][tx], e  = smsh[ty+1][tx+1], f  = smsh[ty+1][tx+2];
        float g  = smsh[ty+2][tx], h2 = smsh[ty+2][tx+1], i2 = smsh[ty+2][tx+2];
        float g0v  = 3.f*(a - c2) + 10.f*(d  - f ) + 3.f*(g  - i2);
        float g90v = 3.f*(a - g ) + 10.f*(bb - h2) + 3.f*(c2 - i2);
        float lap  = 4.f*e - bb - d - f - h2;
        float edge = fmaxf(fabsf(g0v), fabsf(g90v)) + 0.1f*fabsf(lap);
        ep[(y0+ty)*W_ + x0 + tx] = edge;
        lsum += edge;
        lmax = fmaxf(lmax, edge);
    }

#pragma unroll
    for (int off = 16; off; off >>= 1) {
        lsum += __shfl_down_sync(0xffffffffu, lsum, off);
        lmax  = fmaxf(lmax, __shfl_down_sync(0xffffffffu, lmax, off));
    }
    __shared__ float rs[8], rm[8];
    int wid = t >> 5, lane = t & 31;
    if (lane == 0) { rs[wid] = lsum; rm[wid] = lmax; }
    __syncthreads();
    if (t == 0) {
        float s = 0.f, m = 0.f;
#pragma unroll
        for (int wI = 0; wI < 8; ++wI) { s += rs[wI]; m = fmaxf(m, rm[wI]); }
        atomicAdd(&g_sums[bc], s);
        atomicMax(&g_maxbits, __float_as_uint(m));
    }
}

// ---------------- SE MLP: pooled -> scale*inv (tiny, 1 block) ----------------
__global__ void k_se(const float* __restrict__ w_fc1, const float* __restrict__ b_fc1,
                     const float* __restrict__ w_fc2, const float* __restrict__ b_fc2) {
    __shared__ float pooled[B_][CM];
    __shared__ float hsh[B_][4];
    __shared__ float inv_s;
    int t = threadIdx.x;
    if (t == 0) inv_s = 1.f/(__uint_as_float(g_maxbits) + 1e-8f);
    __syncthreads();
    float inv = inv_s;
    if (t < B_*CM)
        pooled[t>>6][t&63] = g_sums[t] * inv * (1.f/(float)HW);
    __syncthreads();
    if (t < B_*4) {
        int b = t >> 2, j = t & 3;
        float z = b_fc1[j];
        for (int c = 0; c < CM; ++c) z += w_fc1[j*CM + c]*pooled[b][c];
        hsh[b][j] = fmaxf(z, 0.f);
    }
    __syncthreads();
    if (t < B_*CM) {
        int b = t >> 6, c = t & 63;
        float z = b_fc2[c];
#pragma unroll
        for (int j = 0; j < 4; ++j) z += w_fc2[c*4 + j]*hsh[b][j];
        g_scale[t] = inv / (1.f + expf(-z));   // sigmoid * inv_max folded
    }
}

// ---------------- fold scale into tf32-rounded output weights (parallel) ----------------
__global__ void k_fold(const float* __restrict__ w_out) {
    int i = blockIdx.x*256 + threadIdx.x;    // 64 blocks -> 16384 = B*CM*CM
    int b = i >> 12, rem = i & 4095, c = rem >> 6, o = rem & 63;
    g_or[i] = tf32_big(w_out[o*CM + c] * g_scale[b*CM + c]);
}

// ---------------- conv1x1 out ----------------
__global__ __launch_bounds__(256, 2)
void k_conv_out(const float* __restrict__ b_out, float* __restrict__ out) {
    int bx = blockIdx.x;
    int b = bx >> 9, tile = bx & 511;
    gemm_body<CM, true>(g_edge + (size_t)b*CM*HW + tile*128,
                        g_or + b*CM*CM, b_out,
                        out + (size_t)b*CM*HW + tile*128);
}

// ---------------- launch ----------------
extern "C" void kernel_launch(void* const* d_in, const int* in_sizes, int n_in,
                              void* d_out, int out_size) {
    const float* x     = (const float*)d_in[0];
    const float* w_in  = (const float*)d_in[1];
    const float* b_in  = (const float*)d_in[2];
    const float* w_fc1 = (const float*)d_in[3];
    const float* b_fc1 = (const float*)d_in[4];
    const float* w_fc2 = (const float*)d_in[5];
    const float* b_fc2 = (const float*)d_in[6];
    const float* w_out = (const float*)d_in[7];
    const float* b_out = (const float*)d_in[8];
    float* out = (float*)d_out;

    k_init<<<64, 256>>>(w_in);
    k_conv_in<<<B_*(HW/128), 256>>>(x, b_in);
    k_edge<<<dim3(W_/TW, H_/TH, B_*CM), 256>>>();
    k_se<<<1, 256>>>(w_fc1, b_fc1, w_fc2, b_fc2);
    k_fold<<<64, 256>>>(w_out);
    k_conv_out<<<B_*(HW/128), 256>>>(b_out, out);
}

// round 10
// speedup vs baseline: 1.2278x; 1.2278x over previous
#include <cuda_runtime.h>

#define B_  4
#define H_  256
#define W_  256
#define CIN 256
#define CM  64
#define HW  (H_*W_)

// ---------------- scratch (static device memory — no allocations) ----------------
__device__ float g_y[(size_t)B_*CM*HW];       // 64 MB: conv_in output
__device__ float g_edge[(size_t)B_*CM*HW];    // 64 MB: edge_raw (pre-normalization)
__device__ float g_wr[CIN*CM];                // w_in tf32-rounded [c][o]
__device__ float g_or[B_*CM*CM];              // folded out weights tf32-rounded [b][c][o]
__device__ float g_scale[B_*CM];              // sigmoid(..)*inv_max per (b,c)
__device__ float g_sums[B_*CM];               // per-(b,c) edge sums
__device__ unsigned int g_maxbits;            // global max (float bits, edge>=0)

// Separable gaussian taps (sigma=2, size=5)
static constexpr double GE0 = 0.6065306597126334;
static constexpr double GE1 = 0.8824969025845955;
static constexpr double GSUM = 2.0*(GE0+GE1)+1.0;
static constexpr float G0 = (float)(GE0/GSUM);
static constexpr float G1 = (float)(GE1/GSUM);
static constexpr float G2 = (float)(1.0/GSUM);

// ---------------- tf32 / async helpers ----------------
__device__ __forceinline__ float tf32_big(float x) {
    unsigned r;
    asm("cvt.rna.tf32.f32 %0, %1;" : "=r"(r) : "f"(x));
    return __uint_as_float(r);
}
__device__ __forceinline__ unsigned tf32_bits(float x) {
    unsigned r;
    asm("cvt.rna.tf32.f32 %0, %1;" : "=r"(r) : "f"(x));
    return r;
}
__device__ __forceinline__ void mma8(float* c, const unsigned* a, unsigned b0, unsigned b1) {
    asm("mma.sync.aligned.m16n8k8.row.col.f32.tf32.tf32.f32 "
        "{%0,%1,%2,%3}, {%4,%5,%6,%7}, {%8,%9}, {%0,%1,%2,%3};"
        : "+f"(c[0]), "+f"(c[1]), "+f"(c[2]), "+f"(c[3])
        : "r"(a[0]), "r"(a[1]), "r"(a[2]), "r"(a[3]), "r"(b0), "r"(b1));
}
__device__ __forceinline__ void cp16(void* smem, const void* g) {
    unsigned s = (unsigned)__cvta_generic_to_shared(smem);
    asm volatile("cp.async.ca.shared.global [%0], [%1], 16;" :: "r"(s), "l"(g));
}
#define CP_COMMIT() asm volatile("cp.async.commit_group;" ::: "memory")
#define CP_WAIT0()  asm volatile("cp.async.wait_group 0;" ::: "memory")

// smem strides (floats); 136,72 == 8 mod 32 -> conflict-free frag LDS; 132 -> conflict-free STS
#define ASTR 136
#define BSTR 72
#define OSTR 132

struct alignas(16) GSmem {
    union {
        struct {
            float xr[2][16*ASTR];   // raw x chunk, double-buffered
            float wr[2][16*BSTR];   // tf32-rounded w chunk
        } s;
        float outs[64*OSTR];
    };
};

// ---------------- 1-term TF32 GEMM body: [KTOT ch] x [128 px] tile -> 64 outs ----------------
// CVT_A=false: feed raw fp32 bits as tf32 (HW conversion; numerically verified benign here).
template<int KTOT, bool CVT_A>
__device__ __forceinline__ void gemm_body(const float* __restrict__ xpx,
                                          const float* __restrict__ wrp,
                                          const float* __restrict__ bias,
                                          float* __restrict__ yout) {
    __shared__ GSmem sm;
    const int t = threadIdx.x;
    const int l = t & 31, wid = t >> 5;
    const int wm = wid & 3, wn = wid >> 2;      // 4 x 2 warp grid (px x out)
    const int lr = l >> 2, lc = l & 3;

    float acc[2][4][4];
#pragma unroll
    for (int mt = 0; mt < 2; ++mt)
#pragma unroll
        for (int nt = 0; nt < 4; ++nt)
#pragma unroll
            for (int q = 0; q < 4; ++q) acc[mt][nt][q] = 0.f;

    // per-thread load indices
    const int xk0 = t >> 5,       xc0 = (t & 31) * 4;   // 2 sub-chunks of 8 ch
    const int wk  = t >> 4,       wc  = (t & 15) * 4;

    // prologue: load chunk 0 into buf 0
    {
        cp16(&sm.s.xr[0][xk0*ASTR + xc0],      xpx + (size_t)xk0*HW + xc0);
        cp16(&sm.s.xr[0][(xk0+8)*ASTR + xc0],  xpx + (size_t)(xk0+8)*HW + xc0);
        cp16(&sm.s.wr[0][wk*BSTR + wc],        wrp + wk*CM + wc);
        CP_COMMIT();
    }

    int buf = 0;
    for (int kc = 0; kc < KTOT; kc += 16) {
        CP_WAIT0();
        __syncthreads();

        // issue next chunk into the other buffer (overlaps with MMA below)
        if (kc + 16 < KTOT) {
            int nb = buf ^ 1, kn = kc + 16;
            cp16(&sm.s.xr[nb][xk0*ASTR + xc0],     xpx + (size_t)(kn+xk0)*HW + xc0);
            cp16(&sm.s.xr[nb][(xk0+8)*ASTR + xc0], xpx + (size_t)(kn+xk0+8)*HW + xc0);
            cp16(&sm.s.wr[nb][wk*BSTR + wc],       wrp + (kn+wk)*CM + wc);
            CP_COMMIT();
        }

        const float* __restrict__ xb = sm.s.xr[buf];
        const float* __restrict__ wb = sm.s.wr[buf];

#pragma unroll
        for (int k8 = 0; k8 < 16; k8 += 8) {
            const int kk = k8 + lc;
            unsigned A[2][4];
#pragma unroll
            for (int mt = 0; mt < 2; ++mt) {
                const int px = wm*32 + mt*16 + lr;
                if (CVT_A) {
                    A[mt][0] = tf32_bits(xb[kk*ASTR + px]);
                    A[mt][1] = tf32_bits(xb[kk*ASTR + px + 8]);
                    A[mt][2] = tf32_bits(xb[(kk+4)*ASTR + px]);
                    A[mt][3] = tf32_bits(xb[(kk+4)*ASTR + px + 8]);
                } else {
                    A[mt][0] = __float_as_uint(xb[kk*ASTR + px]);
                    A[mt][1] = __float_as_uint(xb[kk*ASTR + px + 8]);
                    A[mt][2] = __float_as_uint(xb[(kk+4)*ASTR + px]);
                    A[mt][3] = __float_as_uint(xb[(kk+4)*ASTR + px + 8]);
                }
            }
#pragma unroll
            for (int nt = 0; nt < 4; ++nt) {
                const int n = wn*32 + nt*8 + lr;
                unsigned B0 = __float_as_uint(wb[kk*BSTR + n]);
                unsigned B1 = __float_as_uint(wb[(kk+4)*BSTR + n]);
#pragma unroll
                for (int mt = 0; mt < 2; ++mt)
                    mma8(acc[mt][nt], A[mt], B0, B1);
            }
        }
        __syncthreads();
        buf ^= 1;
    }

    // stage C frags to smem, then coalesced store + bias
#pragma unroll
    for (int mt = 0; mt < 2; ++mt) {
#pragma unroll
        for (int nt = 0; nt < 4; ++nt) {
            int px = wm*32 + mt*16 + lr;
            int o  = wn*32 + nt*8 + 2*lc;
            sm.outs[o*OSTR + px]           = acc[mt][nt][0];
            sm.outs[(o+1)*OSTR + px]       = acc[mt][nt][1];
            sm.outs[o*OSTR + px + 8]       = acc[mt][nt][2];
            sm.outs[(o+1)*OSTR + px + 8]   = acc[mt][nt][3];
        }
    }
    __syncthreads();
#pragma unroll
    for (int p = 0; p < 8; ++p) {
        int i = p*256 + t;
        int o = i >> 5, c4 = (i & 31) * 4;
        float4 v = *(const float4*)&sm.outs[o*OSTR + c4];
        float bv = bias[o];
        v.x += bv; v.y += bv; v.z += bv; v.w += bv;
        *(float4*)(yout + (size_t)o*HW + c4) = v;
    }
}

// ---------------- init: tf32-round w_in, zero reductions ----------------
__global__ void k_init(const float* __restrict__ w_in) {
    int i = blockIdx.x*256 + threadIdx.x;    // 16384 = CIN*CM
    int c = i >> 6, o = i & 63;
    g_wr[i] = tf32_big(w_in[o*CIN + c]);
    if (i < B_*CM) g_sums[i] = 0.f;
    if (i == 0) g_maxbits = 0u;
}

// ---------------- conv1x1 in: [B,256,HW] -> [B,64,HW] ----------------
__global__ __launch_bounds__(256)
void k_conv_in(const float* __restrict__ x, const float* __restrict__ b_in) {
    int bx = blockIdx.x;
    int b = bx >> 9, tile = bx & 511;
    gemm_body<CIN, false>(x + (size_t)b*CIN*HW + tile*128, g_wr, b_in,
                          g_y + (size_t)b*CM*HW + tile*128);
}

// ---------------- fused gaussian(separable) + scharr/laplacian + reductions ----------------
#define TW 64
#define TH 32
__global__ __launch_bounds__(256)
void k_edge() {
    __shared__ float ysh[TH+6][TW+8];
    __shared__ float tsh[TH+6][TW+4];
    __shared__ float smsh[TH+2][TW+4];

    const int t  = threadIdx.x;
    const int x0 = blockIdx.x*TW, y0 = blockIdx.y*TH;
    const int bc = blockIdx.z;
    const float* __restrict__ yp = g_y    + (size_t)bc*HW;
    float* __restrict__       ep = g_edge + (size_t)bc*HW;

    for (int i = t; i < (TH+6)*(TW+6); i += 256) {
        int rr = i/(TW+6), cc = i - rr*(TW+6);
        int gr = y0 - 3 + rr, gc = x0 - 3 + cc;
        float v = 0.f;
        if ((unsigned)gr < H_ && (unsigned)gc < W_) v = yp[gr*W_ + gc];
        ysh[rr][cc] = v;
    }
    __syncthreads();

    for (int i = t; i < (TH+6)*(TW+2); i += 256) {
        int rr = i/(TW+2), jj = i - rr*(TW+2);
        tsh[rr][jj] = G0*(ysh[rr][jj] + ysh[rr][jj+4])
                    + G1*(ysh[rr][jj+1] + ysh[rr][jj+3])
                    + G2* ysh[rr][jj+2];
    }
    __syncthreads();

    for (int i = t; i < (TH+2)*(TW+2); i += 256) {
        int ii = i/(TW+2), jj = i - ii*(TW+2);
        int sr = y0 - 1 + ii, sc = x0 - 1 + jj;
        float v = 0.f;
        if ((unsigned)sr < H_ && (unsigned)sc < W_)
            v = G0*(tsh[ii][jj] + tsh[ii+4][jj])
              + G1*(tsh[ii+1][jj] + tsh[ii+3][jj])
              + G2* tsh[ii+2][jj];
        smsh[ii][jj] = v;
    }
    __syncthreads();

    float lsum = 0.f, lmax = 0.f;
    for (int i = t; i < TH*TW; i += 256) {
        int ty = i >> 6, tx = i & 63;
        float a  = smsh[ty  ][tx], bb = smsh[ty  ][tx+1], c2 = smsh[ty  ][tx+2];
        float d  = smsh[ty+1][tx], e  = smsh[ty+1][tx+1], f  = smsh[ty+1][tx+2];
        float g  = smsh[ty+2][tx], h2 = smsh[ty+2][tx+1], i2 = smsh[ty+2][tx+2];
        float g0v  = 3.f*(a - c2) + 10.f*(d  - f ) + 3.f*(g  - i2);
        float g90v = 3.f*(a - g ) + 10.f*(bb - h2) + 3.f*(c2 - i2);
        float lap  = 4.f*e - bb - d - f - h2;
        float edge = fmaxf(fabsf(g0v), fabsf(g90v)) + 0.1f*fabsf(lap);
        ep[(y0+ty)*W_ + x0 + tx] = edge;
        lsum += edge;
        lmax = fmaxf(lmax, edge);
    }

#pragma unroll
    for (int off = 16; off; off >>= 1) {
        lsum += __shfl_down_sync(0xffffffffu, lsum, off);
        lmax  = fmaxf(lmax, __shfl_down_sync(0xffffffffu, lmax, off));
    }
    __shared__ float rs[8], rm[8];
    int wid = t >> 5, lane = t & 31;
    if (lane == 0) { rs[wid] = lsum; rm[wid] = lmax; }
    __syncthreads();
    if (t == 0) {
        float s = 0.f, m = 0.f;
#pragma unroll
        for (int wI = 0; wI < 8; ++wI) { s += rs[wI]; m = fmaxf(m, rm[wI]); }
        atomicAdd(&g_sums[bc], s);
        atomicMax(&g_maxbits, __float_as_uint(m));
    }
}

// ---------------- SE MLP: pooled -> scale*inv (tiny, 1 block) ----------------
__global__ void k_se(const float* __restrict__ w_fc1, const float* __restrict__ b_fc1,
                     const float* __restrict__ w_fc2, const float* __restrict__ b_fc2) {
    __shared__ float pooled[B_][CM];
    __shared__ float hsh[B_][4];
    __shared__ float inv_s;
    int t = threadIdx.x;
    if (t == 0) inv_s = 1.f/(__uint_as_float(g_maxbits) + 1e-8f);
    __syncthreads();
    float inv = inv_s;
    if (t < B_*CM)
        pooled[t>>6][t&63] = g_sums[t] * inv * (1.f/(float)HW);
    __syncthreads();
    if (t < B_*4) {
        int b = t >> 2, j = t & 3;
        float z = b_fc1[j];
        for (int c = 0; c < CM; ++c) z += w_fc1[j*CM + c]*pooled[b][c];
        hsh[b][j] = fmaxf(z, 0.f);
    }
    __syncthreads();
    if (t < B_*CM) {
        int b = t >> 6, c = t & 63;
        float z = b_fc2[c];
#pragma unroll
        for (int j = 0; j < 4; ++j) z += w_fc2[c*4 + j]*hsh[b][j];
        g_scale[t] = inv / (1.f + expf(-z));   // sigmoid * inv_max folded
    }
}

// ---------------- fold scale into tf32-rounded output weights (parallel) ----------------
__global__ void k_fold(const float* __restrict__ w_out) {
    int i = blockIdx.x*256 + threadIdx.x;    // 64 blocks -> 16384 = B*CM*CM
    int b = i >> 12, rem = i & 4095, c = rem >> 6, o = rem & 63;
    g_or[i] = tf32_big(w_out[o*CM + c] * g_scale[b*CM + c]);
}

// ---------------- conv1x1 out ----------------
__global__ __launch_bounds__(256)
void k_conv_out(const float* __restrict__ b_out, float* __restrict__ out) {
    int bx = blockIdx.x;
    int b = bx >> 9, tile = bx & 511;
    gemm_body<CM, true>(g_edge + (size_t)b*CM*HW + tile*128,
                        g_or + b*CM*CM, b_out,
                        out + (size_t)b*CM*HW + tile*128);
}

// ---------------- launch ----------------
extern "C" void kernel_launch(void* const* d_in, const int* in_sizes, int n_in,
                              void* d_out, int out_size) {
    const float* x     = (const float*)d_in[0];
    const float* w_in  = (const float*)d_in[1];
    const float* b_in  = (const float*)d_in[2];
    const float* w_fc1 = (const float*)d_in[3];
    const float* b_fc1 = (const float*)d_in[4];
    const float* w_fc2 = (const float*)d_in[5];
    const float* b_fc2 = (const float*)d_in[6];
    const float* w_out = (const float*)d_in[7];
    const float* b_out = (const float*)d_in[8];
    float* out = (float*)d_out;

    k_init<<<64, 256>>>(w_in);
    k_conv_in<<<B_*(HW/128), 256>>>(x, b_in);
    k_edge<<<dim3(W_/TW, H_/TH, B_*CM), 256>>>();
    k_se<<<1, 256>>>(w_fc1, b_fc1, w_fc2, b_fc2);
    k_fold<<<64, 256>>>(w_out);
    k_conv_out<<<B_*(HW/128), 256>>>(b_out, out);
}